// round 8
// baseline (speedup 1.0000x reference)
#include <cuda_runtime.h>
#include <cuda_bf16.h>

// Problem constants
#define NN 100000
#define EE 1600000
#define C  128      // IN_C = H1 = H2 = 128
#define OC 64

#define TILE 1024                       // counts per scan block
#define MAXB ((NN + TILE - 1) / TILE)   // 98

// Scratch (allocation-free rule: __device__ globals)
__device__ int   g_cnt[NN];          // in-degree histogram (no self-loop)
__device__ int   g_cursor[NN];       // bucket-fill cursors
__device__ int   g_rowptr[NN + 1];   // CSR row pointers (by target col)
__device__ int   g_blocksum[MAXB + 1];
__device__ int   g_csrsrc[EE];       // CSR source indices
__device__ float g_dinv[NN];
__device__ float g_bufH[(size_t)NN * C];   // h = A*W (raw, no dinv)
__device__ float g_bufG[(size_t)NN * C];   // layer-2 aggregate (+b2)
__device__ float g_bufX[(size_t)NN * C];   // relu(layer1) output

// ---------------------------------------------------------------------------
// CSR build:  zero -> histogram -> dinv -> 3-phase scan -> fill
// edge_index is int32 (JAX x64 disabled): ei[0..e) = row, ei[e..2e) = col.
// ---------------------------------------------------------------------------
__global__ void zero_kernel(int* __restrict__ cnt, int* __restrict__ cursor, int n) {
    int i = blockIdx.x * blockDim.x + threadIdx.x;
    if (i < n) { cnt[i] = 0; cursor[i] = 0; }
}

__global__ void hist_kernel(const int* __restrict__ ei,
                            int* __restrict__ cnt, int e, int n) {
    int i = blockIdx.x * blockDim.x + threadIdx.x;
    if (i < e) {
        int c = ei[e + i];
        if ((unsigned)c < (unsigned)n) atomicAdd(&cnt[c], 1);
    }
}

__global__ void dinv_kernel(const int* __restrict__ cnt,
                            float* __restrict__ dinv, int n) {
    int i = blockIdx.x * blockDim.x + threadIdx.x;
    if (i < n) dinv[i] = rsqrtf((float)cnt[i] + 1.0f);   // +1 self-loop
}

// Phase 1: per-block (1024-count tile) sums
__global__ __launch_bounds__(256) void partial_kernel(
    const int* __restrict__ cnt, int* __restrict__ blocksum, int n)
{
    int t = threadIdx.x;
    int base = blockIdx.x * TILE + t * 4;
    int s = 0;
    #pragma unroll
    for (int k = 0; k < 4; k++)
        if (base + k < n) s += cnt[base + k];

    #pragma unroll
    for (int o = 16; o; o >>= 1) s += __shfl_xor_sync(0xffffffffu, s, o);
    __shared__ int ws[8];
    if ((t & 31) == 0) ws[t >> 5] = s;
    __syncthreads();
    if (t == 0) {
        int tot = 0;
        #pragma unroll
        for (int w = 0; w < 8; w++) tot += ws[w];
        blocksum[blockIdx.x] = tot;
    }
}

// Phase 2: exclusive scan of block sums (nb <= 128); writes rowptr[n] = total
__global__ __launch_bounds__(128) void scan_sums_kernel(
    int* __restrict__ blocksum, int* __restrict__ rowptr, int nb, int n)
{
    int t = threadIdx.x;
    int lane = t & 31;
    int wid  = t >> 5;
    int v = (t < nb) ? blocksum[t] : 0;
    int incl = v;
    #pragma unroll
    for (int o = 1; o < 32; o <<= 1) {
        int x = __shfl_up_sync(0xffffffffu, incl, o);
        if (lane >= o) incl += x;
    }
    __shared__ int ws[4];
    if (lane == 31) ws[wid] = incl;
    __syncthreads();
    int base = 0;
    #pragma unroll
    for (int w = 0; w < 4; w++) base += (w < wid) ? ws[w] : 0;
    if (t < nb) blocksum[t] = base + incl - v;       // exclusive
    if (t == nb - 1) rowptr[n] = base + incl;        // total
}

// Phase 3: local scan per tile + block offset -> rowptr
__global__ __launch_bounds__(256) void write_rowptr_kernel(
    const int* __restrict__ cnt, const int* __restrict__ blocksum,
    int* __restrict__ rowptr, int n)
{
    int t = threadIdx.x;
    int lane = t & 31;
    int wid  = t >> 5;
    int base = blockIdx.x * TILE + t * 4;

    int c[4];
    #pragma unroll
    for (int k = 0; k < 4; k++)
        c[k] = (base + k < n) ? cnt[base + k] : 0;
    int s = c[0] + c[1] + c[2] + c[3];

    int incl = s;
    #pragma unroll
    for (int o = 1; o < 32; o <<= 1) {
        int x = __shfl_up_sync(0xffffffffu, incl, o);
        if (lane >= o) incl += x;
    }
    __shared__ int ws[8];
    if (lane == 31) ws[wid] = incl;
    __syncthreads();
    int wbase = 0;
    #pragma unroll
    for (int w = 0; w < 8; w++) wbase += (w < wid) ? ws[w] : 0;

    int run = blocksum[blockIdx.x] + wbase + incl - s;   // exclusive prefix
    #pragma unroll
    for (int k = 0; k < 4; k++) {
        if (base + k < n) rowptr[base + k] = run;
        run += c[k];
    }
}

__global__ void fill_kernel(const int* __restrict__ ei,
                            const int* __restrict__ rowptr,
                            int* __restrict__ cursor,
                            int* __restrict__ csrsrc, int e, int n)
{
    int i = blockIdx.x * blockDim.x + threadIdx.x;
    if (i < e) {
        int r = ei[i];
        int c = ei[e + i];
        if ((unsigned)r < (unsigned)n && (unsigned)c < (unsigned)n) {
            int pos = atomicAdd(&cursor[c], 1);
            csrsrc[rowptr[c] + pos] = r;
        }
    }
}

// ---------------------------------------------------------------------------
// GEMM (f32x2 packed): [n x 128] @ [128 x 128] -> hs (raw, no dinv).
// 256 threads, tile 64 rows x 128 cols. Thread -> 4 rows x 8 cols,
// inner product via fma.rn.f32x2 (FFMA2): 16 packed FMAs per k.
// ---------------------------------------------------------------------------
__global__ __launch_bounds__(256) void gemm_f32x2_kernel(
    const float* __restrict__ A, const float* __restrict__ W,
    float* __restrict__ hs, int nrows)
{
    __shared__ __align__(16) float As[64][C];    // 32 KB
    __shared__ __align__(16) float Ws[16][C];    //  8 KB
    int t    = threadIdx.x;
    int lane = t & 31;
    int w    = t >> 5;
    int lx   = lane & 15;
    int half = lane >> 4;
    int rbase = (w * 2 + half) * 4;   // 0..60
    int row0  = blockIdx.x * 64;

    // stage A tile (64x128), coalesced float4
    for (int i = t; i < 64 * 32; i += 256) {
        int r = i >> 5, c4 = i & 31;
        int gr = row0 + r;
        float4 v = (gr < nrows)
                     ? reinterpret_cast<const float4*>(A)[(size_t)gr * 32 + c4]
                     : make_float4(0.f, 0.f, 0.f, 0.f);
        reinterpret_cast<float4*>(&As[r][0])[c4] = v;
    }

    unsigned long long acc[4][4];
    #pragma unroll
    for (int r = 0; r < 4; r++)
        #pragma unroll
        for (int j = 0; j < 4; j++) acc[r][j] = 0ULL;   // {0.f, 0.f}

    for (int kc = 0; kc < C; kc += 16) {
        __syncthreads();
        for (int i = t; i < 16 * 32; i += 256) {
            int r = i >> 5, c4 = i & 31;
            reinterpret_cast<float4*>(&Ws[r][0])[c4] =
                reinterpret_cast<const float4*>(W)[(size_t)(kc + r) * 32 + c4];
        }
        __syncthreads();
        #pragma unroll
        for (int kk = 0; kk < 16; kk++) {
            const ulonglong2* Wv = reinterpret_cast<const ulonglong2*>(&Ws[kk][0]);
            ulonglong2 p0 = Wv[lx * 2];
            ulonglong2 p1 = Wv[lx * 2 + 1];
            unsigned long long wp0 = p0.x, wp1 = p0.y, wp2 = p1.x, wp3 = p1.y;
            #pragma unroll
            for (int r = 0; r < 4; r++) {
                float a = As[rbase + r][kc + kk];
                unsigned long long a2;
                asm("mov.b64 %0, {%1, %1};" : "=l"(a2) : "r"(__float_as_uint(a)));
                asm("fma.rn.f32x2 %0, %1, %2, %0;" : "+l"(acc[r][0]) : "l"(a2), "l"(wp0));
                asm("fma.rn.f32x2 %0, %1, %2, %0;" : "+l"(acc[r][1]) : "l"(a2), "l"(wp1));
                asm("fma.rn.f32x2 %0, %1, %2, %0;" : "+l"(acc[r][2]) : "l"(a2), "l"(wp2));
                asm("fma.rn.f32x2 %0, %1, %2, %0;" : "+l"(acc[r][3]) : "l"(a2), "l"(wp3));
            }
        }
    }

    #pragma unroll
    for (int r = 0; r < 4; r++) {
        int gr = row0 + rbase + r;
        if (gr < nrows) {
            unsigned int x0, x1, x2, x3;
            float4 o;
            asm("mov.b64 {%0, %1}, %2;" : "=r"(x0), "=r"(x1) : "l"(acc[r][0]));
            asm("mov.b64 {%0, %1}, %2;" : "=r"(x2), "=r"(x3) : "l"(acc[r][1]));
            o.x = __uint_as_float(x0); o.y = __uint_as_float(x1);
            o.z = __uint_as_float(x2); o.w = __uint_as_float(x3);
            reinterpret_cast<float4*>(hs)[(size_t)gr * 32 + lx * 2] = o;
            asm("mov.b64 {%0, %1}, %2;" : "=r"(x0), "=r"(x1) : "l"(acc[r][2]));
            asm("mov.b64 {%0, %1}, %2;" : "=r"(x2), "=r"(x3) : "l"(acc[r][3]));
            o.x = __uint_as_float(x0); o.y = __uint_as_float(x1);
            o.z = __uint_as_float(x2); o.w = __uint_as_float(x3);
            reinterpret_cast<float4*>(hs)[(size_t)gr * 32 + lx * 2 + 1] = o;
        }
    }
}

// ---------------------------------------------------------------------------
// Gather aggregation: one warp per node. hs is RAW h; dinv applied per edge:
//   out[node] = act( dinv[node] * (h[node]*dinv[node] + sum_j h[r_j]*dinv[r_j]) + bias )
// ---------------------------------------------------------------------------
template<bool RELU>
__global__ __launch_bounds__(256) void gather_kernel(
    const int* __restrict__ rowptr, const int* __restrict__ csrsrc,
    const float* __restrict__ hs, const float* __restrict__ dinv,
    const float* __restrict__ bias, float* __restrict__ out, int n)
{
    int w    = (blockIdx.x * blockDim.x + threadIdx.x) >> 5;
    int lane = threadIdx.x & 31;
    if (w >= n) return;

    const float4* H = reinterpret_cast<const float4*>(hs);
    int start = rowptr[w];
    int end   = rowptr[w + 1];
    float sw  = dinv[w];

    float4 self = H[(size_t)w * 32 + lane];
    float4 acc;
    acc.x = self.x * sw; acc.y = self.y * sw;
    acc.z = self.z * sw; acc.w = self.w * sw;

    int j = start;
    for (; j + 4 <= end; j += 4) {
        int r0 = csrsrc[j], r1 = csrsrc[j+1], r2 = csrsrc[j+2], r3 = csrsrc[j+3];
        float s0 = dinv[r0], s1 = dinv[r1], s2 = dinv[r2], s3 = dinv[r3];
        float4 v0 = H[(size_t)r0 * 32 + lane];
        float4 v1 = H[(size_t)r1 * 32 + lane];
        float4 v2 = H[(size_t)r2 * 32 + lane];
        float4 v3 = H[(size_t)r3 * 32 + lane];
        acc.x = fmaf(v0.x, s0, acc.x); acc.y = fmaf(v0.y, s0, acc.y);
        acc.z = fmaf(v0.z, s0, acc.z); acc.w = fmaf(v0.w, s0, acc.w);
        acc.x = fmaf(v1.x, s1, acc.x); acc.y = fmaf(v1.y, s1, acc.y);
        acc.z = fmaf(v1.z, s1, acc.z); acc.w = fmaf(v1.w, s1, acc.w);
        acc.x = fmaf(v2.x, s2, acc.x); acc.y = fmaf(v2.y, s2, acc.y);
        acc.z = fmaf(v2.z, s2, acc.z); acc.w = fmaf(v2.w, s2, acc.w);
        acc.x = fmaf(v3.x, s3, acc.x); acc.y = fmaf(v3.y, s3, acc.y);
        acc.z = fmaf(v3.z, s3, acc.z); acc.w = fmaf(v3.w, s3, acc.w);
    }
    for (; j < end; j++) {
        int r = csrsrc[j];
        float s = dinv[r];
        float4 v = H[(size_t)r * 32 + lane];
        acc.x = fmaf(v.x, s, acc.x); acc.y = fmaf(v.y, s, acc.y);
        acc.z = fmaf(v.z, s, acc.z); acc.w = fmaf(v.w, s, acc.w);
    }

    float4 bb = reinterpret_cast<const float4*>(bias)[lane];
    acc.x = fmaf(acc.x, sw, bb.x);
    acc.y = fmaf(acc.y, sw, bb.y);
    acc.z = fmaf(acc.z, sw, bb.z);
    acc.w = fmaf(acc.w, sw, bb.w);
    if (RELU) {
        acc.x = fmaxf(acc.x, 0.f); acc.y = fmaxf(acc.y, 0.f);
        acc.z = fmaxf(acc.z, 0.f); acc.w = fmaxf(acc.w, 0.f);
    }
    reinterpret_cast<float4*>(out)[(size_t)w * 32 + lane] = acc;
}

// ---------------------------------------------------------------------------
// Final: per node (one warp): v = agg (b2 already applied); L2-normalize;
// emb out; logits = emb @ Wd + bd; log_softmax; logits out.
// ---------------------------------------------------------------------------
__global__ __launch_bounds__(256) void final_kernel(
    const float* __restrict__ agg,
    const float* __restrict__ Wd, const float* __restrict__ bd,
    float* __restrict__ out_logits, float* __restrict__ out_emb, int n)
{
    __shared__ float Wds[C * OC];     // 32 KB, [k][c] layout
    __shared__ float embS[8][C];      //  4 KB
    int t = threadIdx.x;
    for (int i = t; i < C * OC / 4; i += 256)
        reinterpret_cast<float4*>(Wds)[i] = reinterpret_cast<const float4*>(Wd)[i];
    __syncthreads();

    int lane = t & 31;
    int w    = t >> 5;
    int node = blockIdx.x * 8 + w;
    if (node >= n) return;

    float4 v = reinterpret_cast<const float4*>(agg)[(size_t)node * 32 + lane];

    float ss = v.x * v.x + v.y * v.y + v.z * v.z + v.w * v.w;
    #pragma unroll
    for (int o = 16; o; o >>= 1) ss += __shfl_xor_sync(0xffffffffu, ss, o);
    float inv = 1.0f / (sqrtf(ss) + 1e-12f);

    float4 e;
    e.x = v.x * inv; e.y = v.y * inv; e.z = v.z * inv; e.w = v.w * inv;
    if (out_emb)
        reinterpret_cast<float4*>(out_emb)[(size_t)node * 32 + lane] = e;
    reinterpret_cast<float4*>(&embS[w][0])[lane] = e;
    __syncwarp();

    float l0 = bd[lane], l1 = bd[lane + 32];
    #pragma unroll
    for (int k = 0; k < C; k++) {
        float ek = embS[w][k];
        l0 += ek * Wds[k * OC + lane];
        l1 += ek * Wds[k * OC + lane + 32];
    }

    float m = fmaxf(l0, l1);
    #pragma unroll
    for (int o = 16; o; o >>= 1) m = fmaxf(m, __shfl_xor_sync(0xffffffffu, m, o));
    float s = expf(l0 - m) + expf(l1 - m);
    #pragma unroll
    for (int o = 16; o; o >>= 1) s += __shfl_xor_sync(0xffffffffu, s, o);
    float lse = m + logf(s);

    if (out_logits) {
        out_logits[(size_t)node * OC + lane]      = l0 - lse;
        out_logits[(size_t)node * OC + lane + 32] = l1 - lse;
    }
}

// ---------------------------------------------------------------------------
// launch — CSR build forked onto a second stream, overlapped with GEMM-1.
// ---------------------------------------------------------------------------
extern "C" void kernel_launch(void* const* d_in, const int* in_sizes, int n_in,
                              void* d_out, int out_size)
{
    const float* x  = (const float*)d_in[0];
    const int*   ei = (const int*)d_in[1];    // int32 (JAX x64 disabled)
    const float* W1 = (const float*)d_in[2];
    const float* b1 = (const float*)d_in[3];
    const float* W2 = (const float*)d_in[4];
    const float* b2 = (const float*)d_in[5];
    const float* Wd = (const float*)d_in[6];
    const float* bd = (const float*)d_in[7];

    int n = in_sizes[0] / C;       // 100000
    int e = in_sizes[1] / 2;       // 1600000

    float* out = (float*)d_out;
    float* out_logits = out;
    float* out_emb    = nullptr;
    if ((size_t)out_size >= (size_t)n * (OC + C)) {
        out_emb = out + (size_t)n * OC;
    } else if (out_size == n * C) {
        out_logits = nullptr;
        out_emb    = out;
    }

    int *cnt, *cursor, *rowptr, *csrsrc, *blocksum;
    float *dinv, *bufH, *bufG, *bufX;
    cudaGetSymbolAddress((void**)&cnt,      g_cnt);
    cudaGetSymbolAddress((void**)&cursor,   g_cursor);
    cudaGetSymbolAddress((void**)&rowptr,   g_rowptr);
    cudaGetSymbolAddress((void**)&csrsrc,   g_csrsrc);
    cudaGetSymbolAddress((void**)&blocksum, g_blocksum);
    cudaGetSymbolAddress((void**)&dinv,     g_dinv);
    cudaGetSymbolAddress((void**)&bufH,     g_bufH);
    cudaGetSymbolAddress((void**)&bufG,     g_bufG);
    cudaGetSymbolAddress((void**)&bufX,     g_bufX);

    static cudaStream_t s2 = nullptr;
    static cudaEvent_t evFork = nullptr, evJoin = nullptr;
    if (!s2) {
        cudaStreamCreateWithFlags(&s2, cudaStreamNonBlocking);
        cudaEventCreateWithFlags(&evFork, cudaEventDisableTiming);
        cudaEventCreateWithFlags(&evJoin, cudaEventDisableTiming);
    }

    int nb = (n + 255) / 256;
    int eb = (e + 255) / 256;
    int sb = (n + TILE - 1) / TILE;   // scan blocks (98)

    int gemm_blocks   = (n + 63) / 64;
    int gather_blocks = (int)(((long long)n * 32 + 255) / 256);

    // Fork: CSR build on s2 concurrent with GEMM-1 on main stream
    cudaEventRecord(evFork, 0);
    cudaStreamWaitEvent(s2, evFork, 0);

    zero_kernel<<<nb, 256, 0, s2>>>(cnt, cursor, n);
    hist_kernel<<<eb, 256, 0, s2>>>(ei, cnt, e, n);
    dinv_kernel<<<nb, 256, 0, s2>>>(cnt, dinv, n);
    partial_kernel<<<sb, 256, 0, s2>>>(cnt, blocksum, n);
    scan_sums_kernel<<<1, 128, 0, s2>>>(blocksum, rowptr, sb, n);
    write_rowptr_kernel<<<sb, 256, 0, s2>>>(cnt, blocksum, rowptr, n);
    fill_kernel<<<eb, 256, 0, s2>>>(ei, rowptr, cursor, csrsrc, e, n);
    cudaEventRecord(evJoin, s2);

    gemm_f32x2_kernel<<<gemm_blocks, 256>>>(x, W1, bufH, n);   // concurrent

    // Join
    cudaStreamWaitEvent(0, evJoin, 0);

    // layer 1 aggregate
    gather_kernel<true><<<gather_blocks, 256>>>(rowptr, csrsrc, bufH, dinv, b1, bufX, n);

    // layer 2
    gemm_f32x2_kernel<<<gemm_blocks, 256>>>(bufX, W2, bufH, n);
    gather_kernel<false><<<gather_blocks, 256>>>(rowptr, csrsrc, bufH, dinv, b2, bufG, n);

    // normalize + decode + log_softmax
    final_kernel<<<(n + 7) / 8, 256>>>(bufG, Wd, bd, out_logits, out_emb, n);
}

// round 9
// speedup vs baseline: 1.8913x; 1.8913x over previous
#include <cuda_runtime.h>
#include <cuda_bf16.h>

// Problem constants
#define NN 100000
#define EE 1600000
#define C  128      // IN_C = H1 = H2 = 128
#define OC 64

#define TILE 1024                       // counts per scan block
#define MAXB ((NN + TILE - 1) / TILE)   // 98

// Scratch (allocation-free rule: __device__ globals)
__device__ int   g_cnt[NN];          // in-degree histogram (no self-loop)
__device__ int   g_cursor[NN];       // bucket-fill cursors
__device__ int   g_rowptr[NN + 1];   // CSR row pointers (by target col)
__device__ int   g_blocksum[MAXB + 1];
__device__ int   g_csrsrc[EE];       // CSR source indices
__device__ float g_dinv[NN];
__device__ float g_bufH[(size_t)NN * C];   // hs = (A*W)*dinv[row]
__device__ float g_bufG[(size_t)NN * C];   // layer-2 aggregate (+b2)
__device__ float g_bufX[(size_t)NN * C];   // relu(layer1) output

// ---------------------------------------------------------------------------
// CSR build:  zero -> histogram -> dinv -> 3-phase scan -> fill
// edge_index is int32 (JAX x64 disabled): ei[0..e) = row, ei[e..2e) = col.
// ---------------------------------------------------------------------------
__global__ void zero_kernel(int* __restrict__ cnt, int* __restrict__ cursor, int n) {
    int i = blockIdx.x * blockDim.x + threadIdx.x;
    if (i < n) { cnt[i] = 0; cursor[i] = 0; }
}

__global__ void hist_kernel(const int* __restrict__ ei,
                            int* __restrict__ cnt, int e, int n) {
    int i = blockIdx.x * blockDim.x + threadIdx.x;
    if (i < e) {
        int c = ei[e + i];
        if ((unsigned)c < (unsigned)n) atomicAdd(&cnt[c], 1);
    }
}

__global__ void dinv_kernel(const int* __restrict__ cnt,
                            float* __restrict__ dinv, int n) {
    int i = blockIdx.x * blockDim.x + threadIdx.x;
    if (i < n) dinv[i] = rsqrtf((float)cnt[i] + 1.0f);   // +1 self-loop
}

// Phase 1: per-block (1024-count tile) sums
__global__ __launch_bounds__(256) void partial_kernel(
    const int* __restrict__ cnt, int* __restrict__ blocksum, int n)
{
    int t = threadIdx.x;
    int base = blockIdx.x * TILE + t * 4;
    int s = 0;
    #pragma unroll
    for (int k = 0; k < 4; k++)
        if (base + k < n) s += cnt[base + k];

    #pragma unroll
    for (int o = 16; o; o >>= 1) s += __shfl_xor_sync(0xffffffffu, s, o);
    __shared__ int ws[8];
    if ((t & 31) == 0) ws[t >> 5] = s;
    __syncthreads();
    if (t == 0) {
        int tot = 0;
        #pragma unroll
        for (int w = 0; w < 8; w++) tot += ws[w];
        blocksum[blockIdx.x] = tot;
    }
}

// Phase 2: exclusive scan of block sums (nb <= 128); writes rowptr[n] = total
__global__ __launch_bounds__(128) void scan_sums_kernel(
    int* __restrict__ blocksum, int* __restrict__ rowptr, int nb, int n)
{
    int t = threadIdx.x;
    int lane = t & 31;
    int wid  = t >> 5;
    int v = (t < nb) ? blocksum[t] : 0;
    int incl = v;
    #pragma unroll
    for (int o = 1; o < 32; o <<= 1) {
        int x = __shfl_up_sync(0xffffffffu, incl, o);
        if (lane >= o) incl += x;
    }
    __shared__ int ws[4];
    if (lane == 31) ws[wid] = incl;
    __syncthreads();
    int base = 0;
    #pragma unroll
    for (int w = 0; w < 4; w++) base += (w < wid) ? ws[w] : 0;
    if (t < nb) blocksum[t] = base + incl - v;       // exclusive
    if (t == nb - 1) rowptr[n] = base + incl;        // total
}

// Phase 3: local scan per tile + block offset -> rowptr
__global__ __launch_bounds__(256) void write_rowptr_kernel(
    const int* __restrict__ cnt, const int* __restrict__ blocksum,
    int* __restrict__ rowptr, int n)
{
    int t = threadIdx.x;
    int lane = t & 31;
    int wid  = t >> 5;
    int base = blockIdx.x * TILE + t * 4;

    int c[4];
    #pragma unroll
    for (int k = 0; k < 4; k++)
        c[k] = (base + k < n) ? cnt[base + k] : 0;
    int s = c[0] + c[1] + c[2] + c[3];

    int incl = s;
    #pragma unroll
    for (int o = 1; o < 32; o <<= 1) {
        int x = __shfl_up_sync(0xffffffffu, incl, o);
        if (lane >= o) incl += x;
    }
    __shared__ int ws[8];
    if (lane == 31) ws[wid] = incl;
    __syncthreads();
    int wbase = 0;
    #pragma unroll
    for (int w = 0; w < 8; w++) wbase += (w < wid) ? ws[w] : 0;

    int run = blocksum[blockIdx.x] + wbase + incl - s;   // exclusive prefix
    #pragma unroll
    for (int k = 0; k < 4; k++) {
        if (base + k < n) rowptr[base + k] = run;
        run += c[k];
    }
}

__global__ void fill_kernel(const int* __restrict__ ei,
                            const int* __restrict__ rowptr,
                            int* __restrict__ cursor,
                            int* __restrict__ csrsrc, int e, int n)
{
    int i = blockIdx.x * blockDim.x + threadIdx.x;
    if (i < e) {
        int r = ei[i];
        int c = ei[e + i];
        if ((unsigned)r < (unsigned)n && (unsigned)c < (unsigned)n) {
            int pos = atomicAdd(&cursor[c], 1);
            csrsrc[rowptr[c] + pos] = r;
        }
    }
}

// ---------------------------------------------------------------------------
// GEMM (R7, known-good): [n x 128] @ [128 x 128], epilogue hs = acc*dinv[row].
// Block: 256 threads, tile 64 rows x 128 cols; thread -> 8 rows x 4 cols.
// ---------------------------------------------------------------------------
__global__ __launch_bounds__(256) void gemm_scaled_kernel(
    const float* __restrict__ A, const float* __restrict__ W,
    const float* __restrict__ dinv, float* __restrict__ hs, int nrows)
{
    __shared__ float As[64][C];    // 32 KB
    __shared__ float Ws[16][C];    //  8 KB
    int t  = threadIdx.x;
    int tx = t & 31;
    int ty = t >> 5;
    int row0 = blockIdx.x * 64;

    for (int i = t; i < 64 * 32; i += 256) {
        int r = i >> 5, c4 = i & 31;
        int gr = row0 + r;
        float4 v = (gr < nrows)
                     ? reinterpret_cast<const float4*>(A)[(size_t)gr * 32 + c4]
                     : make_float4(0.f, 0.f, 0.f, 0.f);
        reinterpret_cast<float4*>(&As[r][0])[c4] = v;
    }

    float acc[8][4];
    #pragma unroll
    for (int r = 0; r < 8; r++) { acc[r][0]=acc[r][1]=acc[r][2]=acc[r][3]=0.f; }

    for (int kc = 0; kc < C; kc += 16) {
        __syncthreads();
        for (int i = t; i < 16 * 32; i += 256) {
            int r = i >> 5, c4 = i & 31;
            reinterpret_cast<float4*>(&Ws[r][0])[c4] =
                reinterpret_cast<const float4*>(W)[(size_t)(kc + r) * 32 + c4];
        }
        __syncthreads();
        #pragma unroll
        for (int kk = 0; kk < 16; kk++) {
            float4 w = reinterpret_cast<float4*>(&Ws[kk][0])[tx];
            #pragma unroll
            for (int r = 0; r < 8; r++) {
                float a = As[ty * 8 + r][kc + kk];
                acc[r][0] += a * w.x;
                acc[r][1] += a * w.y;
                acc[r][2] += a * w.z;
                acc[r][3] += a * w.w;
            }
        }
    }

    #pragma unroll
    for (int r = 0; r < 8; r++) {
        int gr = row0 + ty * 8 + r;
        if (gr < nrows) {
            float s = dinv[gr];
            float4 h;
            h.x = acc[r][0] * s;  h.y = acc[r][1] * s;
            h.z = acc[r][2] * s;  h.w = acc[r][3] * s;
            reinterpret_cast<float4*>(hs)[(size_t)gr * 32 + tx] = h;
        }
    }
}

// ---------------------------------------------------------------------------
// Gather aggregation: one warp per node, unroll-8 for MLP.
//   out[node] = act( (hs[node] + sum_j hs[src_j]) * dinv[node] + bias )
// ---------------------------------------------------------------------------
template<bool RELU>
__global__ __launch_bounds__(256) void gather_kernel(
    const int* __restrict__ rowptr, const int* __restrict__ csrsrc,
    const float* __restrict__ hs, const float* __restrict__ dinv,
    const float* __restrict__ bias, float* __restrict__ out, int n)
{
    int w    = (blockIdx.x * blockDim.x + threadIdx.x) >> 5;
    int lane = threadIdx.x & 31;
    if (w >= n) return;

    const float4* H = reinterpret_cast<const float4*>(hs);
    int start = rowptr[w];
    int end   = rowptr[w + 1];

    float4 acc = H[(size_t)w * 32 + lane];    // self contribution
    float4 acc2 = make_float4(0.f, 0.f, 0.f, 0.f);

    int j = start;
    for (; j + 8 <= end; j += 8) {
        int r0 = csrsrc[j],   r1 = csrsrc[j+1], r2 = csrsrc[j+2], r3 = csrsrc[j+3];
        int r4 = csrsrc[j+4], r5 = csrsrc[j+5], r6 = csrsrc[j+6], r7 = csrsrc[j+7];
        float4 v0 = H[(size_t)r0 * 32 + lane];
        float4 v1 = H[(size_t)r1 * 32 + lane];
        float4 v2 = H[(size_t)r2 * 32 + lane];
        float4 v3 = H[(size_t)r3 * 32 + lane];
        float4 v4 = H[(size_t)r4 * 32 + lane];
        float4 v5 = H[(size_t)r5 * 32 + lane];
        float4 v6 = H[(size_t)r6 * 32 + lane];
        float4 v7 = H[(size_t)r7 * 32 + lane];
        acc.x  += v0.x + v1.x; acc.y  += v0.y + v1.y;
        acc.z  += v0.z + v1.z; acc.w  += v0.w + v1.w;
        acc2.x += v2.x + v3.x; acc2.y += v2.y + v3.y;
        acc2.z += v2.z + v3.z; acc2.w += v2.w + v3.w;
        acc.x  += v4.x + v5.x; acc.y  += v4.y + v5.y;
        acc.z  += v4.z + v5.z; acc.w  += v4.w + v5.w;
        acc2.x += v6.x + v7.x; acc2.y += v6.y + v7.y;
        acc2.z += v6.z + v7.z; acc2.w += v6.w + v7.w;
    }
    for (; j + 4 <= end; j += 4) {
        int r0 = csrsrc[j], r1 = csrsrc[j+1], r2 = csrsrc[j+2], r3 = csrsrc[j+3];
        float4 v0 = H[(size_t)r0 * 32 + lane];
        float4 v1 = H[(size_t)r1 * 32 + lane];
        float4 v2 = H[(size_t)r2 * 32 + lane];
        float4 v3 = H[(size_t)r3 * 32 + lane];
        acc.x  += v0.x + v1.x; acc.y  += v0.y + v1.y;
        acc.z  += v0.z + v1.z; acc.w  += v0.w + v1.w;
        acc2.x += v2.x + v3.x; acc2.y += v2.y + v3.y;
        acc2.z += v2.z + v3.z; acc2.w += v2.w + v3.w;
    }
    for (; j < end; j++) {
        int r = csrsrc[j];
        float4 v = H[(size_t)r * 32 + lane];
        acc.x += v.x; acc.y += v.y; acc.z += v.z; acc.w += v.w;
    }
    acc.x += acc2.x; acc.y += acc2.y; acc.z += acc2.z; acc.w += acc2.w;

    float s  = dinv[w];
    float4 bb = reinterpret_cast<const float4*>(bias)[lane];
    acc.x = fmaf(acc.x, s, bb.x);
    acc.y = fmaf(acc.y, s, bb.y);
    acc.z = fmaf(acc.z, s, bb.z);
    acc.w = fmaf(acc.w, s, bb.w);
    if (RELU) {
        acc.x = fmaxf(acc.x, 0.f); acc.y = fmaxf(acc.y, 0.f);
        acc.z = fmaxf(acc.z, 0.f); acc.w = fmaxf(acc.w, 0.f);
    }
    reinterpret_cast<float4*>(out)[(size_t)w * 32 + lane] = acc;
}

// ---------------------------------------------------------------------------
// Final: per node (one warp): v = agg (b2 already applied); L2-normalize;
// emb out; logits = emb @ Wd + bd; log_softmax; logits out.
// ---------------------------------------------------------------------------
__global__ __launch_bounds__(256) void final_kernel(
    const float* __restrict__ agg,
    const float* __restrict__ Wd, const float* __restrict__ bd,
    float* __restrict__ out_logits, float* __restrict__ out_emb, int n)
{
    __shared__ float Wds[C * OC];     // 32 KB, [k][c] layout
    __shared__ float embS[8][C];      //  4 KB
    int t = threadIdx.x;
    for (int i = t; i < C * OC / 4; i += 256)
        reinterpret_cast<float4*>(Wds)[i] = reinterpret_cast<const float4*>(Wd)[i];
    __syncthreads();

    int lane = t & 31;
    int w    = t >> 5;
    int node = blockIdx.x * 8 + w;
    if (node >= n) return;

    float4 v = reinterpret_cast<const float4*>(agg)[(size_t)node * 32 + lane];

    float ss = v.x * v.x + v.y * v.y + v.z * v.z + v.w * v.w;
    #pragma unroll
    for (int o = 16; o; o >>= 1) ss += __shfl_xor_sync(0xffffffffu, ss, o);
    float inv = 1.0f / (sqrtf(ss) + 1e-12f);

    float4 e;
    e.x = v.x * inv; e.y = v.y * inv; e.z = v.z * inv; e.w = v.w * inv;
    if (out_emb)
        reinterpret_cast<float4*>(out_emb)[(size_t)node * 32 + lane] = e;
    reinterpret_cast<float4*>(&embS[w][0])[lane] = e;
    __syncwarp();

    float l0 = bd[lane], l1 = bd[lane + 32];
    #pragma unroll
    for (int k = 0; k < C; k++) {
        float ek = embS[w][k];
        l0 += ek * Wds[k * OC + lane];
        l1 += ek * Wds[k * OC + lane + 32];
    }

    float m = fmaxf(l0, l1);
    #pragma unroll
    for (int o = 16; o; o >>= 1) m = fmaxf(m, __shfl_xor_sync(0xffffffffu, m, o));
    float s = expf(l0 - m) + expf(l1 - m);
    #pragma unroll
    for (int o = 16; o; o >>= 1) s += __shfl_xor_sync(0xffffffffu, s, o);
    float lse = m + logf(s);

    if (out_logits) {
        out_logits[(size_t)node * OC + lane]      = l0 - lse;
        out_logits[(size_t)node * OC + lane + 32] = l1 - lse;
    }
}

// ---------------------------------------------------------------------------
// launch — zero/hist/dinv on main (GEMM-1 needs dinv), then scan+fill tail
// forked onto stream 2 concurrent with GEMM-1.
// ---------------------------------------------------------------------------
extern "C" void kernel_launch(void* const* d_in, const int* in_sizes, int n_in,
                              void* d_out, int out_size)
{
    const float* x  = (const float*)d_in[0];
    const int*   ei = (const int*)d_in[1];    // int32 (JAX x64 disabled)
    const float* W1 = (const float*)d_in[2];
    const float* b1 = (const float*)d_in[3];
    const float* W2 = (const float*)d_in[4];
    const float* b2 = (const float*)d_in[5];
    const float* Wd = (const float*)d_in[6];
    const float* bd = (const float*)d_in[7];

    int n = in_sizes[0] / C;       // 100000
    int e = in_sizes[1] / 2;       // 1600000

    float* out = (float*)d_out;
    float* out_logits = out;
    float* out_emb    = nullptr;
    if ((size_t)out_size >= (size_t)n * (OC + C)) {
        out_emb = out + (size_t)n * OC;
    } else if (out_size == n * C) {
        out_logits = nullptr;
        out_emb    = out;
    }

    int *cnt, *cursor, *rowptr, *csrsrc, *blocksum;
    float *dinv, *bufH, *bufG, *bufX;
    cudaGetSymbolAddress((void**)&cnt,      g_cnt);
    cudaGetSymbolAddress((void**)&cursor,   g_cursor);
    cudaGetSymbolAddress((void**)&rowptr,   g_rowptr);
    cudaGetSymbolAddress((void**)&csrsrc,   g_csrsrc);
    cudaGetSymbolAddress((void**)&blocksum, g_blocksum);
    cudaGetSymbolAddress((void**)&dinv,     g_dinv);
    cudaGetSymbolAddress((void**)&bufH,     g_bufH);
    cudaGetSymbolAddress((void**)&bufG,     g_bufG);
    cudaGetSymbolAddress((void**)&bufX,     g_bufX);

    static cudaStream_t s2 = nullptr;
    static cudaEvent_t evFork = nullptr, evJoin = nullptr;
    if (!s2) {
        cudaStreamCreateWithFlags(&s2, cudaStreamNonBlocking);
        cudaEventCreateWithFlags(&evFork, cudaEventDisableTiming);
        cudaEventCreateWithFlags(&evJoin, cudaEventDisableTiming);
    }

    int nb = (n + 255) / 256;
    int eb = (e + 255) / 256;
    int sb = (n + TILE - 1) / TILE;   // scan blocks (98)

    int gemm_blocks   = (n + 63) / 64;
    int gather_blocks = (int)(((long long)n * 32 + 255) / 256);

    // Prefix of CSR build on main stream (GEMM-1 needs dinv)
    zero_kernel<<<nb, 256>>>(cnt, cursor, n);
    hist_kernel<<<eb, 256>>>(ei, cnt, e, n);
    dinv_kernel<<<nb, 256>>>(cnt, dinv, n);

    // Fork: scan+fill tail on s2, concurrent with GEMM-1 on main stream
    cudaEventRecord(evFork, 0);
    cudaStreamWaitEvent(s2, evFork, 0);
    partial_kernel<<<sb, 256, 0, s2>>>(cnt, blocksum, n);
    scan_sums_kernel<<<1, 128, 0, s2>>>(blocksum, rowptr, sb, n);
    write_rowptr_kernel<<<sb, 256, 0, s2>>>(cnt, blocksum, rowptr, n);
    fill_kernel<<<eb, 256, 0, s2>>>(ei, rowptr, cursor, csrsrc, e, n);
    cudaEventRecord(evJoin, s2);

    gemm_scaled_kernel<<<gemm_blocks, 256>>>(x, W1, dinv, bufH, n);  // concurrent

    // Join
    cudaStreamWaitEvent(0, evJoin, 0);

    // layer 1 aggregate
    gather_kernel<true><<<gather_blocks, 256>>>(rowptr, csrsrc, bufH, dinv, b1, bufX, n);

    // layer 2
    gemm_scaled_kernel<<<gemm_blocks, 256>>>(bufX, W2, dinv, bufH, n);
    gather_kernel<false><<<gather_blocks, 256>>>(rowptr, csrsrc, bufH, dinv, b2, bufG, n);

    // normalize + decode + log_softmax
    final_kernel<<<(n + 7) / 8, 256>>>(bufG, Wd, bd, out_logits, out_emb, n);
}

// round 12
// speedup vs baseline: 1.9921x; 1.0533x over previous
#include <cuda_runtime.h>
#include <cuda_fp16.h>

// Problem constants
#define NN 100000
#define EE 1600000
#define C  128      // IN_C = H1 = H2 = 128
#define OC 64

#define TILE 1024                       // counts per scan block
#define MAXB ((NN + TILE - 1) / TILE)   // 98

// Scratch (allocation-free rule: __device__ globals)
__device__ int    g_cnt[NN];          // in-degree histogram (no self-loop)
__device__ int    g_cursor[NN];       // bucket-fill cursors
__device__ int    g_rowptr[NN + 1];   // CSR row pointers (by target col)
__device__ int    g_blocksum[MAXB + 1];
__device__ int    g_csrsrc[EE];       // CSR source indices
__device__ float  g_dinv[NN];
__device__ __half g_bufH[(size_t)NN * C];  // hs = (A*W)*dinv[row], fp16 messages
__device__ float  g_bufG[(size_t)NN * C];  // layer-2 aggregate (+b2)
__device__ float  g_bufX[(size_t)NN * C];  // relu(layer1) output

// ---------------------------------------------------------------------------
// CSR build:  zero -> histogram -> dinv -> 3-phase scan -> fill
// edge_index is int32 (JAX x64 disabled): ei[0..e) = row, ei[e..2e) = col.
// ---------------------------------------------------------------------------
__global__ void zero_kernel(int* __restrict__ cnt, int* __restrict__ cursor, int n) {
    int i = blockIdx.x * blockDim.x + threadIdx.x;
    if (i < n) { cnt[i] = 0; cursor[i] = 0; }
}

__global__ void hist_kernel(const int* __restrict__ ei,
                            int* __restrict__ cnt, int e, int n) {
    int i = blockIdx.x * blockDim.x + threadIdx.x;
    if (i < e) {
        int c = ei[e + i];
        if ((unsigned)c < (unsigned)n) atomicAdd(&cnt[c], 1);
    }
}

__global__ void dinv_kernel(const int* __restrict__ cnt,
                            float* __restrict__ dinv, int n) {
    int i = blockIdx.x * blockDim.x + threadIdx.x;
    if (i < n) dinv[i] = rsqrtf((float)cnt[i] + 1.0f);   // +1 self-loop
}

// Phase 1: per-block (1024-count tile) sums
__global__ __launch_bounds__(256) void partial_kernel(
    const int* __restrict__ cnt, int* __restrict__ blocksum, int n)
{
    int t = threadIdx.x;
    int base = blockIdx.x * TILE + t * 4;
    int s = 0;
    #pragma unroll
    for (int k = 0; k < 4; k++)
        if (base + k < n) s += cnt[base + k];

    #pragma unroll
    for (int o = 16; o; o >>= 1) s += __shfl_xor_sync(0xffffffffu, s, o);
    __shared__ int ws[8];
    if ((t & 31) == 0) ws[t >> 5] = s;
    __syncthreads();
    if (t == 0) {
        int tot = 0;
        #pragma unroll
        for (int w = 0; w < 8; w++) tot += ws[w];
        blocksum[blockIdx.x] = tot;
    }
}

// Phase 2: exclusive scan of block sums (nb <= 128); writes rowptr[n] = total
__global__ __launch_bounds__(128) void scan_sums_kernel(
    int* __restrict__ blocksum, int* __restrict__ rowptr, int nb, int n)
{
    int t = threadIdx.x;
    int lane = t & 31;
    int wid  = t >> 5;
    int v = (t < nb) ? blocksum[t] : 0;
    int incl = v;
    #pragma unroll
    for (int o = 1; o < 32; o <<= 1) {
        int x = __shfl_up_sync(0xffffffffu, incl, o);
        if (lane >= o) incl += x;
    }
    __shared__ int ws[4];
    if (lane == 31) ws[wid] = incl;
    __syncthreads();
    int base = 0;
    #pragma unroll
    for (int w = 0; w < 4; w++) base += (w < wid) ? ws[w] : 0;
    if (t < nb) blocksum[t] = base + incl - v;       // exclusive
    if (t == nb - 1) rowptr[n] = base + incl;        // total
}

// Phase 3: local scan per tile + block offset -> rowptr
__global__ __launch_bounds__(256) void write_rowptr_kernel(
    const int* __restrict__ cnt, const int* __restrict__ blocksum,
    int* __restrict__ rowptr, int n)
{
    int t = threadIdx.x;
    int lane = t & 31;
    int wid  = t >> 5;
    int base = blockIdx.x * TILE + t * 4;

    int c[4];
    #pragma unroll
    for (int k = 0; k < 4; k++)
        c[k] = (base + k < n) ? cnt[base + k] : 0;
    int s = c[0] + c[1] + c[2] + c[3];

    int incl = s;
    #pragma unroll
    for (int o = 1; o < 32; o <<= 1) {
        int x = __shfl_up_sync(0xffffffffu, incl, o);
        if (lane >= o) incl += x;
    }
    __shared__ int ws[8];
    if (lane == 31) ws[wid] = incl;
    __syncthreads();
    int wbase = 0;
    #pragma unroll
    for (int w = 0; w < 8; w++) wbase += (w < wid) ? ws[w] : 0;

    int run = blocksum[blockIdx.x] + wbase + incl - s;   // exclusive prefix
    #pragma unroll
    for (int k = 0; k < 4; k++) {
        if (base + k < n) rowptr[base + k] = run;
        run += c[k];
    }
}

__global__ void fill_kernel(const int* __restrict__ ei,
                            const int* __restrict__ rowptr,
                            int* __restrict__ cursor,
                            int* __restrict__ csrsrc, int e, int n)
{
    int i = blockIdx.x * blockDim.x + threadIdx.x;
    if (i < e) {
        int r = ei[i];
        int c = ei[e + i];
        if ((unsigned)r < (unsigned)n && (unsigned)c < (unsigned)n) {
            int pos = atomicAdd(&cursor[c], 1);
            csrsrc[rowptr[c] + pos] = r;
        }
    }
}

// ---------------------------------------------------------------------------
// GEMM: [n x 128] @ [128 x 128], epilogue hs = half(acc*dinv[row]).
// Block: 256 threads, tile 64 rows x 128 cols; thread -> 8 rows x 4 cols.
// ---------------------------------------------------------------------------
__global__ __launch_bounds__(256) void gemm_scaled_kernel(
    const float* __restrict__ A, const float* __restrict__ W,
    const float* __restrict__ dinv, __half* __restrict__ hs, int nrows)
{
    __shared__ float As[64][C];    // 32 KB
    __shared__ float Ws[16][C];    //  8 KB
    int t  = threadIdx.x;
    int tx = t & 31;
    int ty = t >> 5;
    int row0 = blockIdx.x * 64;

    for (int i = t; i < 64 * 32; i += 256) {
        int r = i >> 5, c4 = i & 31;
        int gr = row0 + r;
        float4 v = (gr < nrows)
                     ? reinterpret_cast<const float4*>(A)[(size_t)gr * 32 + c4]
                     : make_float4(0.f, 0.f, 0.f, 0.f);
        reinterpret_cast<float4*>(&As[r][0])[c4] = v;
    }

    float acc[8][4];
    #pragma unroll
    for (int r = 0; r < 8; r++) { acc[r][0]=acc[r][1]=acc[r][2]=acc[r][3]=0.f; }

    for (int kc = 0; kc < C; kc += 16) {
        __syncthreads();
        for (int i = t; i < 16 * 32; i += 256) {
            int r = i >> 5, c4 = i & 31;
            reinterpret_cast<float4*>(&Ws[r][0])[c4] =
                reinterpret_cast<const float4*>(W)[(size_t)(kc + r) * 32 + c4];
        }
        __syncthreads();
        #pragma unroll
        for (int kk = 0; kk < 16; kk++) {
            float4 w = reinterpret_cast<float4*>(&Ws[kk][0])[tx];
            #pragma unroll
            for (int r = 0; r < 8; r++) {
                float a = As[ty * 8 + r][kc + kk];
                acc[r][0] += a * w.x;
                acc[r][1] += a * w.y;
                acc[r][2] += a * w.z;
                acc[r][3] += a * w.w;
            }
        }
    }

    #pragma unroll
    for (int r = 0; r < 8; r++) {
        int gr = row0 + ty * 8 + r;
        if (gr < nrows) {
            float s = dinv[gr];
            __half2 h01 = __floats2half2_rn(acc[r][0] * s, acc[r][1] * s);
            __half2 h23 = __floats2half2_rn(acc[r][2] * s, acc[r][3] * s);
            uint2 u;
            u.x = *reinterpret_cast<unsigned int*>(&h01);
            u.y = *reinterpret_cast<unsigned int*>(&h23);
            reinterpret_cast<uint2*>(hs)[(size_t)gr * 32 + tx] = u;
        }
    }
}

// ---------------------------------------------------------------------------
// Gather aggregation: one warp per node, fp16 messages, fp32 accumulate.
//   out[node] = act( (hs[node] + sum_j hs[src_j]) * dinv[node] + bias )
// Each lane owns 4 channels: one uint2 (4 halfs, 8B) per edge.
// ---------------------------------------------------------------------------
__device__ __forceinline__ void acc_u2(float4& a, uint2 u) {
    float2 f01 = __half22float2(*reinterpret_cast<__half2*>(&u.x));
    float2 f23 = __half22float2(*reinterpret_cast<__half2*>(&u.y));
    a.x += f01.x; a.y += f01.y; a.z += f23.x; a.w += f23.y;
}

template<bool RELU>
__global__ __launch_bounds__(256) void gather_kernel(
    const int* __restrict__ rowptr, const int* __restrict__ csrsrc,
    const __half* __restrict__ hs, const float* __restrict__ dinv,
    const float* __restrict__ bias, float* __restrict__ out, int n)
{
    int w    = (blockIdx.x * blockDim.x + threadIdx.x) >> 5;
    int lane = threadIdx.x & 31;
    if (w >= n) return;

    const uint2* H = reinterpret_cast<const uint2*>(hs);
    int start = rowptr[w];
    int end   = rowptr[w + 1];

    float4 acc  = make_float4(0.f, 0.f, 0.f, 0.f);
    float4 acc2 = make_float4(0.f, 0.f, 0.f, 0.f);
    acc_u2(acc, H[(size_t)w * 32 + lane]);            // self contribution

    int j = start;
    for (; j + 8 <= end; j += 8) {
        int r0 = csrsrc[j],   r1 = csrsrc[j+1], r2 = csrsrc[j+2], r3 = csrsrc[j+3];
        int r4 = csrsrc[j+4], r5 = csrsrc[j+5], r6 = csrsrc[j+6], r7 = csrsrc[j+7];
        uint2 u0 = H[(size_t)r0 * 32 + lane];
        uint2 u1 = H[(size_t)r1 * 32 + lane];
        uint2 u2 = H[(size_t)r2 * 32 + lane];
        uint2 u3 = H[(size_t)r3 * 32 + lane];
        uint2 u4 = H[(size_t)r4 * 32 + lane];
        uint2 u5 = H[(size_t)r5 * 32 + lane];
        uint2 u6 = H[(size_t)r6 * 32 + lane];
        uint2 u7 = H[(size_t)r7 * 32 + lane];
        acc_u2(acc,  u0); acc_u2(acc2, u1);
        acc_u2(acc,  u2); acc_u2(acc2, u3);
        acc_u2(acc,  u4); acc_u2(acc2, u5);
        acc_u2(acc,  u6); acc_u2(acc2, u7);
    }
    for (; j < end; j++) {
        int r = csrsrc[j];
        acc_u2(acc, H[(size_t)r * 32 + lane]);
    }
    acc.x += acc2.x; acc.y += acc2.y; acc.z += acc2.z; acc.w += acc2.w;

    float s  = dinv[w];
    float4 bb = reinterpret_cast<const float4*>(bias)[lane];
    acc.x = fmaf(acc.x, s, bb.x);
    acc.y = fmaf(acc.y, s, bb.y);
    acc.z = fmaf(acc.z, s, bb.z);
    acc.w = fmaf(acc.w, s, bb.w);
    if (RELU) {
        acc.x = fmaxf(acc.x, 0.f); acc.y = fmaxf(acc.y, 0.f);
        acc.z = fmaxf(acc.z, 0.f); acc.w = fmaxf(acc.w, 0.f);
    }
    reinterpret_cast<float4*>(out)[(size_t)w * 32 + lane] = acc;
}

// ---------------------------------------------------------------------------
// Final: per node (one warp): v = agg (b2 already applied); L2-normalize;
// emb out; logits = emb @ Wd + bd; log_softmax; logits out.
// ---------------------------------------------------------------------------
__global__ __launch_bounds__(256) void final_kernel(
    const float* __restrict__ agg,
    const float* __restrict__ Wd, const float* __restrict__ bd,
    float* __restrict__ out_logits, float* __restrict__ out_emb, int n)
{
    __shared__ float Wds[C * OC];     // 32 KB, [k][c] layout
    __shared__ float embS[8][C];      //  4 KB
    int t = threadIdx.x;
    for (int i = t; i < C * OC / 4; i += 256)
        reinterpret_cast<float4*>(Wds)[i] = reinterpret_cast<const float4*>(Wd)[i];
    __syncthreads();

    int lane = t & 31;
    int w    = t >> 5;
    int node = blockIdx.x * 8 + w;
    if (node >= n) return;

    float4 v = reinterpret_cast<const float4*>(agg)[(size_t)node * 32 + lane];

    float ss = v.x * v.x + v.y * v.y + v.z * v.z + v.w * v.w;
    #pragma unroll
    for (int o = 16; o; o >>= 1) ss += __shfl_xor_sync(0xffffffffu, ss, o);
    float inv = 1.0f / (sqrtf(ss) + 1e-12f);

    float4 e;
    e.x = v.x * inv; e.y = v.y * inv; e.z = v.z * inv; e.w = v.w * inv;
    if (out_emb)
        reinterpret_cast<float4*>(out_emb)[(size_t)node * 32 + lane] = e;
    reinterpret_cast<float4*>(&embS[w][0])[lane] = e;
    __syncwarp();

    float l0 = bd[lane], l1 = bd[lane + 32];
    #pragma unroll
    for (int k = 0; k < C; k++) {
        float ek = embS[w][k];
        l0 += ek * Wds[k * OC + lane];
        l1 += ek * Wds[k * OC + lane + 32];
    }

    float m = fmaxf(l0, l1);
    #pragma unroll
    for (int o = 16; o; o >>= 1) m = fmaxf(m, __shfl_xor_sync(0xffffffffu, m, o));
    float s = expf(l0 - m) + expf(l1 - m);
    #pragma unroll
    for (int o = 16; o; o >>= 1) s += __shfl_xor_sync(0xffffffffu, s, o);
    float lse = m + logf(s);

    if (out_logits) {
        out_logits[(size_t)node * OC + lane]      = l0 - lse;
        out_logits[(size_t)node * OC + lane + 32] = l1 - lse;
    }
}

// ---------------------------------------------------------------------------
// launch — zero/hist/dinv on main (GEMM-1 needs dinv), then scan+fill tail
// forked onto stream 2 concurrent with GEMM-1.
// ---------------------------------------------------------------------------
extern "C" void kernel_launch(void* const* d_in, const int* in_sizes, int n_in,
                              void* d_out, int out_size)
{
    const float* x  = (const float*)d_in[0];
    const int*   ei = (const int*)d_in[1];    // int32 (JAX x64 disabled)
    const float* W1 = (const float*)d_in[2];
    const float* b1 = (const float*)d_in[3];
    const float* W2 = (const float*)d_in[4];
    const float* b2 = (const float*)d_in[5];
    const float* Wd = (const float*)d_in[6];
    const float* bd = (const float*)d_in[7];

    int n = in_sizes[0] / C;       // 100000
    int e = in_sizes[1] / 2;       // 1600000

    float* out = (float*)d_out;
    float* out_logits = out;
    float* out_emb    = nullptr;
    if ((size_t)out_size >= (size_t)n * (OC + C)) {
        out_emb = out + (size_t)n * OC;
    } else if (out_size == n * C) {
        out_logits = nullptr;
        out_emb    = out;
    }

    int *cnt, *cursor, *rowptr, *csrsrc, *blocksum;
    float *dinv, *bufG, *bufX;
    __half* bufH;
    cudaGetSymbolAddress((void**)&cnt,      g_cnt);
    cudaGetSymbolAddress((void**)&cursor,   g_cursor);
    cudaGetSymbolAddress((void**)&rowptr,   g_rowptr);
    cudaGetSymbolAddress((void**)&csrsrc,   g_csrsrc);
    cudaGetSymbolAddress((void**)&blocksum, g_blocksum);
    cudaGetSymbolAddress((void**)&dinv,     g_dinv);
    cudaGetSymbolAddress((void**)&bufH,     g_bufH);
    cudaGetSymbolAddress((void**)&bufG,     g_bufG);
    cudaGetSymbolAddress((void**)&bufX,     g_bufX);

    static cudaStream_t s2 = nullptr;
    static cudaEvent_t evFork = nullptr, evJoin = nullptr;
    if (!s2) {
        cudaStreamCreateWithFlags(&s2, cudaStreamNonBlocking);
        cudaEventCreateWithFlags(&evFork, cudaEventDisableTiming);
        cudaEventCreateWithFlags(&evJoin, cudaEventDisableTiming);
    }

    int nb = (n + 255) / 256;
    int eb = (e + 255) / 256;
    int sb = (n + TILE - 1) / TILE;   // scan blocks (98)

    int gemm_blocks   = (n + 63) / 64;
    int gather_blocks = (int)(((long long)n * 32 + 255) / 256);

    // Prefix of CSR build on main stream (GEMM-1 needs dinv)
    zero_kernel<<<nb, 256>>>(cnt, cursor, n);
    hist_kernel<<<eb, 256>>>(ei, cnt, e, n);
    dinv_kernel<<<nb, 256>>>(cnt, dinv, n);

    // Fork: scan+fill tail on s2, concurrent with GEMM-1 on main stream
    cudaEventRecord(evFork, 0);
    cudaStreamWaitEvent(s2, evFork, 0);
    partial_kernel<<<sb, 256, 0, s2>>>(cnt, blocksum, n);
    scan_sums_kernel<<<1, 128, 0, s2>>>(blocksum, rowptr, sb, n);
    write_rowptr_kernel<<<sb, 256, 0, s2>>>(cnt, blocksum, rowptr, n);
    fill_kernel<<<eb, 256, 0, s2>>>(ei, rowptr, cursor, csrsrc, e, n);
    cudaEventRecord(evJoin, s2);

    gemm_scaled_kernel<<<gemm_blocks, 256>>>(x, W1, dinv, bufH, n);  // concurrent

    // Join
    cudaStreamWaitEvent(0, evJoin, 0);

    // layer 1 aggregate
    gather_kernel<true><<<gather_blocks, 256>>>(rowptr, csrsrc, bufH, dinv, b1, bufX, n);

    // layer 2
    gemm_scaled_kernel<<<gemm_blocks, 256>>>(bufX, W2, dinv, bufH, n);
    gather_kernel<false><<<gather_blocks, 256>>>(rowptr, csrsrc, bufH, dinv, b2, bufG, n);

    // normalize + decode + log_softmax
    final_kernel<<<(n + 7) / 8, 256>>>(bufG, Wd, bd, out_logits, out_emb, n);
}

// round 14
// speedup vs baseline: 2.4676x; 1.2387x over previous
#include <cuda_runtime.h>
#include <cuda_fp16.h>
#include <cstdint>

// Problem constants
#define NN 100000
#define EE 1600000
#define C  128      // IN_C = H1 = H2 = 128
#define OC 64

#define TILE 1024                       // counts per scan block
#define MAXB ((NN + TILE - 1) / TILE)   // 98
#define AP 136                          // padded half-stride (272 B) for MMA smem

// Scratch (allocation-free rule: __device__ globals)
__device__ int    g_cnt[NN];          // in-degree histogram (no self-loop)
__device__ int    g_cursor[NN];       // bucket-fill cursors
__device__ int    g_rowptr[NN + 1];   // CSR row pointers (by target col)
__device__ int    g_blocksum[MAXB + 1];
__device__ int    g_csrsrc[EE];       // CSR source indices
__device__ float  g_dinv[NN];
__device__ __half g_bufH[(size_t)NN * C];  // hs = (A*W)*dinv[row], fp16 messages
__device__ float  g_bufG[(size_t)NN * C];  // layer-2 aggregate (+b2)
__device__ float  g_bufX[(size_t)NN * C];  // relu(layer1) output

// ---------------------------------------------------------------------------
// CSR build:  zero -> histogram -> dinv -> 3-phase scan -> fill
// edge_index is int32 (JAX x64 disabled): ei[0..e) = row, ei[e..2e) = col.
// ---------------------------------------------------------------------------
__global__ void zero_kernel(int* __restrict__ cnt, int* __restrict__ cursor, int n) {
    int i = blockIdx.x * blockDim.x + threadIdx.x;
    if (i < n) { cnt[i] = 0; cursor[i] = 0; }
}

__global__ void hist_kernel(const int* __restrict__ ei,
                            int* __restrict__ cnt, int e, int n) {
    int i = blockIdx.x * blockDim.x + threadIdx.x;
    if (i < e) {
        int c = ei[e + i];
        if ((unsigned)c < (unsigned)n) atomicAdd(&cnt[c], 1);
    }
}

__global__ void dinv_kernel(const int* __restrict__ cnt,
                            float* __restrict__ dinv, int n) {
    int i = blockIdx.x * blockDim.x + threadIdx.x;
    if (i < n) dinv[i] = rsqrtf((float)cnt[i] + 1.0f);   // +1 self-loop
}

// Phase 1: per-block (1024-count tile) sums
__global__ __launch_bounds__(256) void partial_kernel(
    const int* __restrict__ cnt, int* __restrict__ blocksum, int n)
{
    int t = threadIdx.x;
    int base = blockIdx.x * TILE + t * 4;
    int s = 0;
    #pragma unroll
    for (int k = 0; k < 4; k++)
        if (base + k < n) s += cnt[base + k];

    #pragma unroll
    for (int o = 16; o; o >>= 1) s += __shfl_xor_sync(0xffffffffu, s, o);
    __shared__ int ws[8];
    if ((t & 31) == 0) ws[t >> 5] = s;
    __syncthreads();
    if (t == 0) {
        int tot = 0;
        #pragma unroll
        for (int w = 0; w < 8; w++) tot += ws[w];
        blocksum[blockIdx.x] = tot;
    }
}

// Phase 2: exclusive scan of block sums (nb <= 128); writes rowptr[n] = total
__global__ __launch_bounds__(128) void scan_sums_kernel(
    int* __restrict__ blocksum, int* __restrict__ rowptr, int nb, int n)
{
    int t = threadIdx.x;
    int lane = t & 31;
    int wid  = t >> 5;
    int v = (t < nb) ? blocksum[t] : 0;
    int incl = v;
    #pragma unroll
    for (int o = 1; o < 32; o <<= 1) {
        int x = __shfl_up_sync(0xffffffffu, incl, o);
        if (lane >= o) incl += x;
    }
    __shared__ int ws[4];
    if (lane == 31) ws[wid] = incl;
    __syncthreads();
    int base = 0;
    #pragma unroll
    for (int w = 0; w < 4; w++) base += (w < wid) ? ws[w] : 0;
    if (t < nb) blocksum[t] = base + incl - v;       // exclusive
    if (t == nb - 1) rowptr[n] = base + incl;        // total
}

// Phase 3: local scan per tile + block offset -> rowptr
__global__ __launch_bounds__(256) void write_rowptr_kernel(
    const int* __restrict__ cnt, const int* __restrict__ blocksum,
    int* __restrict__ rowptr, int n)
{
    int t = threadIdx.x;
    int lane = t & 31;
    int wid  = t >> 5;
    int base = blockIdx.x * TILE + t * 4;

    int c[4];
    #pragma unroll
    for (int k = 0; k < 4; k++)
        c[k] = (base + k < n) ? cnt[base + k] : 0;
    int s = c[0] + c[1] + c[2] + c[3];

    int incl = s;
    #pragma unroll
    for (int o = 1; o < 32; o <<= 1) {
        int x = __shfl_up_sync(0xffffffffu, incl, o);
        if (lane >= o) incl += x;
    }
    __shared__ int ws[8];
    if (lane == 31) ws[wid] = incl;
    __syncthreads();
    int wbase = 0;
    #pragma unroll
    for (int w = 0; w < 8; w++) wbase += (w < wid) ? ws[w] : 0;

    int run = blocksum[blockIdx.x] + wbase + incl - s;   // exclusive prefix
    #pragma unroll
    for (int k = 0; k < 4; k++) {
        if (base + k < n) rowptr[base + k] = run;
        run += c[k];
    }
}

__global__ void fill_kernel(const int* __restrict__ ei,
                            const int* __restrict__ rowptr,
                            int* __restrict__ cursor,
                            int* __restrict__ csrsrc, int e, int n)
{
    int i = blockIdx.x * blockDim.x + threadIdx.x;
    if (i < e) {
        int r = ei[i];
        int c = ei[e + i];
        if ((unsigned)r < (unsigned)n && (unsigned)c < (unsigned)n) {
            int pos = atomicAdd(&cursor[c], 1);
            csrsrc[rowptr[c] + pos] = r;
        }
    }
}

// ---------------------------------------------------------------------------
// HMMA GEMM: [n x 128] @ [128 x 128] -> hs = half(acc * dinv[row]).
// fp16 inputs (converted in staging), fp32 accumulators via
// mma.sync.m16n8k16. Block 256 thr, tile 64 rows x 128 cols; warp w handles
// rows (w%4)*16..+16, cols (w/4)*64..+64. W staged in two 64-k-row halves
// (2 x 17.4 KB) to stay under the 48 KB static smem limit. Rows padded to
// AP=136 halfs (272 B): row-to-row bank offset = 4 -> conflict-free ldmatrix.
// ---------------------------------------------------------------------------
__device__ __forceinline__ void ldm_x4(unsigned int& r0, unsigned int& r1,
                                       unsigned int& r2, unsigned int& r3,
                                       unsigned int a) {
    asm volatile("ldmatrix.sync.aligned.m8n8.x4.shared.b16 {%0,%1,%2,%3}, [%4];"
                 : "=r"(r0), "=r"(r1), "=r"(r2), "=r"(r3) : "r"(a));
}
__device__ __forceinline__ void ldm_x4_t(unsigned int& r0, unsigned int& r1,
                                         unsigned int& r2, unsigned int& r3,
                                         unsigned int a) {
    asm volatile("ldmatrix.sync.aligned.m8n8.x4.trans.shared.b16 {%0,%1,%2,%3}, [%4];"
                 : "=r"(r0), "=r"(r1), "=r"(r2), "=r"(r3) : "r"(a));
}
__device__ __forceinline__ void mma16816(float* c,
                                         unsigned int a0, unsigned int a1,
                                         unsigned int a2, unsigned int a3,
                                         unsigned int b0, unsigned int b1) {
    asm volatile("mma.sync.aligned.m16n8k16.row.col.f32.f16.f16.f32 "
                 "{%0,%1,%2,%3}, {%4,%5,%6,%7}, {%8,%9}, {%0,%1,%2,%3};"
                 : "+f"(c[0]), "+f"(c[1]), "+f"(c[2]), "+f"(c[3])
                 : "r"(a0), "r"(a1), "r"(a2), "r"(a3), "r"(b0), "r"(b1));
}

__global__ __launch_bounds__(256) void gemm_hmma_kernel(
    const float* __restrict__ A, const float* __restrict__ W,
    const float* __restrict__ dinv, __half* __restrict__ hs, int nrows)
{
    __shared__ __half As[64 * AP];   // 17.4 KB
    __shared__ __half Ws[64 * AP];   // 17.4 KB (one 64-k-row half of W)
    int t    = threadIdx.x;
    int lane = t & 31;
    int w    = t >> 5;
    int row0 = blockIdx.x * 64;

    // stage A tile (64 x 128 fp32 -> fp16), coalesced float2 loads
    for (int i = t; i < 64 * 64; i += 256) {
        int r = i >> 6, c2 = i & 63;
        int gr = row0 + r;
        float2 v = (gr < nrows)
                     ? reinterpret_cast<const float2*>(A)[(size_t)gr * 64 + c2]
                     : make_float2(0.f, 0.f);
        *reinterpret_cast<__half2*>(&As[r * AP + c2 * 2]) = __floats2half2_rn(v.x, v.y);
    }

    int mrow = (w & 3) * 16;
    int ncol = (w >> 2) * 64;

    float acc[8][4];
    #pragma unroll
    for (int i = 0; i < 8; i++) {
        #pragma unroll
        for (int j = 0; j < 4; j++) acc[i][j] = 0.f;
    }

    unsigned int a_base = (unsigned int)__cvta_generic_to_shared(As);
    unsigned int w_base = (unsigned int)__cvta_generic_to_shared(Ws);

    #pragma unroll
    for (int hstep = 0; hstep < 2; hstep++) {
        if (hstep) __syncthreads();    // previous Ws readers done
        // stage W rows [hstep*64, hstep*64+64)
        for (int i = t; i < 64 * 64; i += 256) {
            int r = i >> 6, c2 = i & 63;
            float2 v = reinterpret_cast<const float2*>(W)[(size_t)(hstep * 64 + r) * 64 + c2];
            *reinterpret_cast<__half2*>(&Ws[r * AP + c2 * 2]) = __floats2half2_rn(v.x, v.y);
        }
        __syncthreads();              // covers A staging on first iter too

        #pragma unroll
        for (int kl = 0; kl < 64; kl += 16) {
            int kg = hstep * 64 + kl;  // global k for A
            unsigned int a_addr = a_base +
                (unsigned int)(((mrow + (lane & 15)) * AP + kg + ((lane >> 4) << 3)) * 2);
            unsigned int a0, a1, a2, a3;
            ldm_x4(a0, a1, a2, a3, a_addr);

            #pragma unroll
            for (int nt = 0; nt < 4; nt++) {
                int n0 = ncol + nt * 16;
                unsigned int b_addr = w_base +
                    (unsigned int)(((kl + (lane & 15)) * AP + n0 + ((lane >> 4) << 3)) * 2);
                unsigned int b0, b1, b2, b3;
                ldm_x4_t(b0, b1, b2, b3, b_addr);
                mma16816(acc[nt * 2],     a0, a1, a2, a3, b0, b1);
                mma16816(acc[nt * 2 + 1], a0, a1, a2, a3, b2, b3);
            }
        }
    }

    // epilogue: C frag lane map: c0,c1 -> row lane/4, cols (lane%4)*2+{0,1};
    // c2,c3 -> row lane/4+8. Scale by dinv[row], write half2.
    int r_lo = mrow + (lane >> 2);
    int r_hi = r_lo + 8;
    int c0   = (lane & 3) * 2;
    int gr_lo = row0 + r_lo, gr_hi = row0 + r_hi;
    float s_lo = (gr_lo < nrows) ? dinv[gr_lo] : 0.f;
    float s_hi = (gr_hi < nrows) ? dinv[gr_hi] : 0.f;
    #pragma unroll
    for (int nt = 0; nt < 8; nt++) {
        int col = ncol + nt * 8 + c0;
        if (gr_lo < nrows) {
            __half2 h2v = __floats2half2_rn(acc[nt][0] * s_lo, acc[nt][1] * s_lo);
            *reinterpret_cast<__half2*>(&hs[(size_t)gr_lo * C + col]) = h2v;
        }
        if (gr_hi < nrows) {
            __half2 h2v = __floats2half2_rn(acc[nt][2] * s_hi, acc[nt][3] * s_hi);
            *reinterpret_cast<__half2*>(&hs[(size_t)gr_hi * C + col]) = h2v;
        }
    }
}

// ---------------------------------------------------------------------------
// Gather aggregation: one warp per node, fp16 messages, fp32 accumulate.
//   out[node] = act( (hs[node] + sum_j hs[src_j]) * dinv[node] + bias )
// Each lane owns 4 channels: one uint2 (4 halfs, 8B) per edge.
// ---------------------------------------------------------------------------
__device__ __forceinline__ void acc_u2(float4& a, uint2 u) {
    float2 f01 = __half22float2(*reinterpret_cast<__half2*>(&u.x));
    float2 f23 = __half22float2(*reinterpret_cast<__half2*>(&u.y));
    a.x += f01.x; a.y += f01.y; a.z += f23.x; a.w += f23.y;
}

template<bool RELU>
__global__ __launch_bounds__(256) void gather_kernel(
    const int* __restrict__ rowptr, const int* __restrict__ csrsrc,
    const __half* __restrict__ hs, const float* __restrict__ dinv,
    const float* __restrict__ bias, float* __restrict__ out, int n)
{
    int w    = (blockIdx.x * blockDim.x + threadIdx.x) >> 5;
    int lane = threadIdx.x & 31;
    if (w >= n) return;

    const uint2* H = reinterpret_cast<const uint2*>(hs);
    int start = rowptr[w];
    int end   = rowptr[w + 1];

    float4 acc  = make_float4(0.f, 0.f, 0.f, 0.f);
    float4 acc2 = make_float4(0.f, 0.f, 0.f, 0.f);
    acc_u2(acc, H[(size_t)w * 32 + lane]);            // self contribution

    int j = start;
    for (; j + 8 <= end; j += 8) {
        int r0 = csrsrc[j],   r1 = csrsrc[j+1], r2 = csrsrc[j+2], r3 = csrsrc[j+3];
        int r4 = csrsrc[j+4], r5 = csrsrc[j+5], r6 = csrsrc[j+6], r7 = csrsrc[j+7];
        uint2 u0 = H[(size_t)r0 * 32 + lane];
        uint2 u1 = H[(size_t)r1 * 32 + lane];
        uint2 u2 = H[(size_t)r2 * 32 + lane];
        uint2 u3 = H[(size_t)r3 * 32 + lane];
        uint2 u4 = H[(size_t)r4 * 32 + lane];
        uint2 u5 = H[(size_t)r5 * 32 + lane];
        uint2 u6 = H[(size_t)r6 * 32 + lane];
        uint2 u7 = H[(size_t)r7 * 32 + lane];
        acc_u2(acc,  u0); acc_u2(acc2, u1);
        acc_u2(acc,  u2); acc_u2(acc2, u3);
        acc_u2(acc,  u4); acc_u2(acc2, u5);
        acc_u2(acc,  u6); acc_u2(acc2, u7);
    }
    for (; j < end; j++) {
        int r = csrsrc[j];
        acc_u2(acc, H[(size_t)r * 32 + lane]);
    }
    acc.x += acc2.x; acc.y += acc2.y; acc.z += acc2.z; acc.w += acc2.w;

    float s  = dinv[w];
    float4 bb = reinterpret_cast<const float4*>(bias)[lane];
    acc.x = fmaf(acc.x, s, bb.x);
    acc.y = fmaf(acc.y, s, bb.y);
    acc.z = fmaf(acc.z, s, bb.z);
    acc.w = fmaf(acc.w, s, bb.w);
    if (RELU) {
        acc.x = fmaxf(acc.x, 0.f); acc.y = fmaxf(acc.y, 0.f);
        acc.z = fmaxf(acc.z, 0.f); acc.w = fmaxf(acc.w, 0.f);
    }
    reinterpret_cast<float4*>(out)[(size_t)w * 32 + lane] = acc;
}

// ---------------------------------------------------------------------------
// Final: per node (one warp): v = agg (b2 already applied); L2-normalize;
// emb out; logits = emb @ Wd + bd; log_softmax; logits out.
// ---------------------------------------------------------------------------
__global__ __launch_bounds__(256) void final_kernel(
    const float* __restrict__ agg,
    const float* __restrict__ Wd, const float* __restrict__ bd,
    float* __restrict__ out_logits, float* __restrict__ out_emb, int n)
{
    __shared__ float Wds[C * OC];     // 32 KB, [k][c] layout
    __shared__ float embS[8][C];      //  4 KB
    int t = threadIdx.x;
    for (int i = t; i < C * OC / 4; i += 256)
        reinterpret_cast<float4*>(Wds)[i] = reinterpret_cast<const float4*>(Wd)[i];
    __syncthreads();

    int lane = t & 31;
    int w    = t >> 5;
    int node = blockIdx.x * 8 + w;
    if (node >= n) return;

    float4 v = reinterpret_cast<const float4*>(agg)[(size_t)node * 32 + lane];

    float ss = v.x * v.x + v.y * v.y + v.z * v.z + v.w * v.w;
    #pragma unroll
    for (int o = 16; o; o >>= 1) ss += __shfl_xor_sync(0xffffffffu, ss, o);
    float inv = 1.0f / (sqrtf(ss) + 1e-12f);

    float4 ev;
    ev.x = v.x * inv; ev.y = v.y * inv; ev.z = v.z * inv; ev.w = v.w * inv;
    if (out_emb)
        reinterpret_cast<float4*>(out_emb)[(size_t)node * 32 + lane] = ev;
    reinterpret_cast<float4*>(&embS[w][0])[lane] = ev;
    __syncwarp();

    float l0 = bd[lane], l1 = bd[lane + 32];
    #pragma unroll
    for (int k = 0; k < C; k++) {
        float ek = embS[w][k];
        l0 += ek * Wds[k * OC + lane];
        l1 += ek * Wds[k * OC + lane + 32];
    }

    float m = fmaxf(l0, l1);
    #pragma unroll
    for (int o = 16; o; o >>= 1) m = fmaxf(m, __shfl_xor_sync(0xffffffffu, m, o));
    float s = expf(l0 - m) + expf(l1 - m);
    #pragma unroll
    for (int o = 16; o; o >>= 1) s += __shfl_xor_sync(0xffffffffu, s, o);
    float lse = m + logf(s);

    if (out_logits) {
        out_logits[(size_t)node * OC + lane]      = l0 - lse;
        out_logits[(size_t)node * OC + lane + 32] = l1 - lse;
    }
}

// ---------------------------------------------------------------------------
// launch — zero/hist/dinv on main (GEMM-1 needs dinv), then scan+fill tail
// forked onto stream 2 concurrent with GEMM-1.
// ---------------------------------------------------------------------------
extern "C" void kernel_launch(void* const* d_in, const int* in_sizes, int n_in,
                              void* d_out, int out_size)
{
    const float* x  = (const float*)d_in[0];
    const int*   ei = (const int*)d_in[1];    // int32 (JAX x64 disabled)
    const float* W1 = (const float*)d_in[2];
    const float* b1 = (const float*)d_in[3];
    const float* W2 = (const float*)d_in[4];
    const float* b2 = (const float*)d_in[5];
    const float* Wd = (const float*)d_in[6];
    const float* bd = (const float*)d_in[7];

    int n = in_sizes[0] / C;       // 100000
    int e = in_sizes[1] / 2;       // 1600000

    float* out = (float*)d_out;
    float* out_logits = out;
    float* out_emb    = nullptr;
    if ((size_t)out_size >= (size_t)n * (OC + C)) {
        out_emb = out + (size_t)n * OC;
    } else if (out_size == n * C) {
        out_logits = nullptr;
        out_emb    = out;
    }

    int *cnt, *cursor, *rowptr, *csrsrc, *blocksum;
    float *dinv, *bufG, *bufX;
    __half* bufH;
    cudaGetSymbolAddress((void**)&cnt,      g_cnt);
    cudaGetSymbolAddress((void**)&cursor,   g_cursor);
    cudaGetSymbolAddress((void**)&rowptr,   g_rowptr);
    cudaGetSymbolAddress((void**)&csrsrc,   g_csrsrc);
    cudaGetSymbolAddress((void**)&blocksum, g_blocksum);
    cudaGetSymbolAddress((void**)&dinv,     g_dinv);
    cudaGetSymbolAddress((void**)&bufH,     g_bufH);
    cudaGetSymbolAddress((void**)&bufG,     g_bufG);
    cudaGetSymbolAddress((void**)&bufX,     g_bufX);

    static cudaStream_t s2 = nullptr;
    static cudaEvent_t evFork = nullptr, evJoin = nullptr;
    if (!s2) {
        cudaStreamCreateWithFlags(&s2, cudaStreamNonBlocking);
        cudaEventCreateWithFlags(&evFork, cudaEventDisableTiming);
        cudaEventCreateWithFlags(&evJoin, cudaEventDisableTiming);
    }

    int nb = (n + 255) / 256;
    int eb = (e + 255) / 256;
    int sb = (n + TILE - 1) / TILE;   // scan blocks (98)

    int gemm_blocks   = (n + 63) / 64;
    int gather_blocks = (int)(((long long)n * 32 + 255) / 256);

    // Prefix of CSR build on main stream (GEMM-1 needs dinv)
    zero_kernel<<<nb, 256>>>(cnt, cursor, n);
    hist_kernel<<<eb, 256>>>(ei, cnt, e, n);
    dinv_kernel<<<nb, 256>>>(cnt, dinv, n);

    // Fork: scan+fill tail on s2, concurrent with GEMM-1 on main stream
    cudaEventRecord(evFork, 0);
    cudaStreamWaitEvent(s2, evFork, 0);
    partial_kernel<<<sb, 256, 0, s2>>>(cnt, blocksum, n);
    scan_sums_kernel<<<1, 128, 0, s2>>>(blocksum, rowptr, sb, n);
    write_rowptr_kernel<<<sb, 256, 0, s2>>>(cnt, blocksum, rowptr, n);
    fill_kernel<<<eb, 256, 0, s2>>>(ei, rowptr, cursor, csrsrc, e, n);
    cudaEventRecord(evJoin, s2);

    gemm_hmma_kernel<<<gemm_blocks, 256>>>(x, W1, dinv, bufH, n);  // concurrent

    // Join
    cudaStreamWaitEvent(0, evJoin, 0);

    // layer 1 aggregate
    gather_kernel<true><<<gather_blocks, 256>>>(rowptr, csrsrc, bufH, dinv, b1, bufX, n);

    // layer 2
    gemm_hmma_kernel<<<gemm_blocks, 256>>>(bufX, W2, dinv, bufH, n);
    gather_kernel<false><<<gather_blocks, 256>>>(rowptr, csrsrc, bufH, dinv, b2, bufG, n);

    // normalize + decode + log_softmax
    final_kernel<<<(n + 7) / 8, 256>>>(bufG, Wd, bd, out_logits, out_emb, n);
}